// round 16
// baseline (speedup 1.0000x reference)
#include <cuda_runtime.h>
#include <cuda_bf16.h>
#include <stdint.h>
#include <math.h>

#define NN 10000
#define NE 80000
#define MT (NE + NN)          /* 90000 edges incl. self loops */
#define K0 512
#define F1 4096
#define F2 1024
#define F3 7

#if defined(__CUDA_ARCH__) && defined(__CUDA_ARCH_FEAT_SM103_ALL)
#define TC_OK 1
#else
#define TC_OK 0
#endif

/* ---------------- scratch (device globals; no allocations allowed) -------- */
__device__ float g_h2[NN * (size_t)F2];
__device__ float g_o2[NN * (size_t)F2];
__device__ float g_h3[NN * F3];
__device__ float g_s[NN];
__device__ float g_d[NN];
__device__ float g_ws1[K0];
__device__ float g_wd1[K0];
__device__ float g_ws2[F1];
__device__ float g_wd2[F1];
__device__ int   g_deg[NN];
__device__ int   g_rowptr[NN + 1];
__device__ int   g_cursor[NN];
__device__ int   g_csrc[MT];
/* pre-split operands (bf16) */
__device__ __nv_bfloat16 g_xahi[(size_t)NN * K0];   /* aggregated x, split */
__device__ __nv_bfloat16 g_xalo[(size_t)NN * K0];
__device__ __nv_bfloat16 g_a1hi[(size_t)NN * F1];   /* o1 split */
__device__ __nv_bfloat16 g_a1lo[(size_t)NN * F1];
__device__ __nv_bfloat16 g_w1hi[(size_t)F1 * K0];
__device__ __nv_bfloat16 g_w1lo[(size_t)F1 * K0];
__device__ __nv_bfloat16 g_w2hi[(size_t)F2 * F1];
__device__ __nv_bfloat16 g_w2lo[(size_t)F2 * F1];

/* ================= tcgen05 helpers (inline PTX) ========================== */
__device__ __forceinline__ uint32_t smem_u32(const void* p) {
    uint32_t a;
    asm("{ .reg .u64 t; cvta.to.shared.u64 t, %1; cvt.u32.u64 %0, t; }"
        : "=r"(a) : "l"(p));
    return a;
}
#if TC_OK
__device__ __forceinline__ uint32_t elect1() {
    uint32_t r;
    asm volatile("{ .reg .pred p; elect.sync _|p, 0xFFFFFFFF; selp.b32 %0,1,0,p; }"
                 : "=r"(r));
    return r;
}
__device__ __forceinline__ void mma_f16_ss(uint32_t d, uint64_t ad, uint64_t bd,
                                           uint32_t idesc, bool accum) {
    uint32_t en = accum ? 1u : 0u;
    asm volatile(
        "{\n\t.reg .pred p;\n\tsetp.ne.u32 p, %5, 0;\n\t"
        "tcgen05.mma.cta_group::1.kind::f16 [%0], %1, %2, %3, {%4,%4,%4,%4}, p;\n\t}"
        :: "r"(d), "l"(ad), "l"(bd), "r"(idesc), "r"(0u), "r"(en) : "memory");
}
#define TC_COMMIT(mbar) \
    asm volatile("tcgen05.commit.cta_group::1.mbarrier::arrive::one.shared::cluster.b64 [%0];" \
                 :: "r"((uint32_t)(mbar)) : "memory")
#define MBAR_INIT(a, c) \
    asm volatile("mbarrier.init.shared.b64 [%0], %1;" :: "r"((uint32_t)(a)), "r"((uint32_t)(c)) : "memory")
#define MBAR_WAIT(a, ph) do { \
    uint32_t _m = (uint32_t)(a); uint32_t _p = (uint32_t)(ph); uint32_t _done; \
    asm volatile("{\n\t.reg .pred p;\n\t" \
        "mbarrier.try_wait.parity.acquire.cta.shared::cta.b64 p, [%1], %2;\n\t" \
        "selp.b32 %0, 1, 0, p;\n\t}" : "=r"(_done) : "r"(_m), "r"(_p) : "memory"); \
    if (!_done) { \
        asm volatile("{\n\t.reg .pred P1;\n\t" \
            "WL_%=:\n\t" \
            "mbarrier.try_wait.parity.acquire.cta.shared::cta.b64 P1, [%0], %1, 0x989680;\n\t" \
            "@P1 bra.uni WD_%=;\n\t" \
            "bra.uni WL_%=;\n\t" \
            "WD_%=:\n\t}" :: "r"(_m), "r"(_p) : "memory"); \
    } } while (0)
#define LDTM_X32(r, a) \
    asm volatile("tcgen05.ld.sync.aligned.32x32b.x32.b32 " \
        "{%0,%1,%2,%3,%4,%5,%6,%7,%8,%9,%10,%11,%12,%13,%14,%15," \
        "%16,%17,%18,%19,%20,%21,%22,%23,%24,%25,%26,%27,%28,%29,%30,%31}, [%32];" \
        : "=r"((r)[0]),"=r"((r)[1]),"=r"((r)[2]),"=r"((r)[3]),"=r"((r)[4]),"=r"((r)[5]),"=r"((r)[6]),"=r"((r)[7]), \
          "=r"((r)[8]),"=r"((r)[9]),"=r"((r)[10]),"=r"((r)[11]),"=r"((r)[12]),"=r"((r)[13]),"=r"((r)[14]),"=r"((r)[15]), \
          "=r"((r)[16]),"=r"((r)[17]),"=r"((r)[18]),"=r"((r)[19]),"=r"((r)[20]),"=r"((r)[21]),"=r"((r)[22]),"=r"((r)[23]), \
          "=r"((r)[24]),"=r"((r)[25]),"=r"((r)[26]),"=r"((r)[27]),"=r"((r)[28]),"=r"((r)[29]),"=r"((r)[30]),"=r"((r)[31]) \
        : "r"(a))
#define TC_WAIT_LD()  asm volatile("tcgen05.wait::ld.sync.aligned;" ::: "memory")
#define TC_FENCE_AFTER() asm volatile("tcgen05.fence::after_thread_sync;" ::: "memory")
#define FENCE_ASYNC() asm volatile("fence.proxy.async.shared::cta;" ::: "memory")
#define CP16(sa, ga) \
    asm volatile("cp.async.cg.shared.global [%0], [%1], 16;" \
                 :: "r"((uint32_t)(sa)), "l"(ga) : "memory")
#define CP_COMMIT() asm volatile("cp.async.commit_group;" ::: "memory")
#define CP_WAIT0()  asm volatile("cp.async.wait_group 0;" ::: "memory")
#endif /* TC_OK */
#define SWZ(x) ((x) ^ (((x) >> 3) & 0x70))

static constexpr unsigned long long DESC_BASE =
    (2ull << 61) | (1ull << 46) | (64ull << 32) | (1ull << 16);
__device__ __forceinline__ uint64_t mk_desc(uint32_t addr) {
    return DESC_BASE | ((uint64_t)(addr >> 4) & 0x3FFF);
}

/* ---- fp32 -> (hi, lo) bf16 ---- */
__device__ __forceinline__ void split1(float x, __nv_bfloat16* h, __nv_bfloat16* l) {
    __nv_bfloat16 hb = __float2bfloat16(x);
    *h = hb;
    *l = __float2bfloat16(x - __bfloat162float(hb));
}
__device__ __forceinline__ float lrelu(float v) {
    return (v > 0.f) ? v : 0.2f * v;
}

/* ---- transpose + split weights + fused attention-MV ---------------------- */
/* W[K][N] -> hiT/loT [N][K] bf16; also o1[k] += W[k,:].v1, o2[k] += W[k,:].v2 */
__global__ void tsplit(const float* __restrict__ W, __nv_bfloat16* __restrict__ hiT,
                       __nv_bfloat16* __restrict__ loT,
                       const float* __restrict__ v1, const float* __restrict__ v2,
                       float* __restrict__ o1, float* __restrict__ o2, int K, int N)
{
    __shared__ float t[32][33];
    int n0 = blockIdx.x * 32, k0 = blockIdx.y * 32;
    int tx = threadIdx.x, ty = threadIdx.y;
    float w = W[(size_t)(k0 + ty) * N + n0 + tx];
    t[ty][tx] = w;
    /* fused dots: warp ty owns W row (k0+ty), lanes span n0+tx */
    float p1 = w * v1[n0 + tx];
    float p2 = w * v2[n0 + tx];
    #pragma unroll
    for (int off = 16; off > 0; off >>= 1) {
        p1 += __shfl_xor_sync(0xffffffffu, p1, off);
        p2 += __shfl_xor_sync(0xffffffffu, p2, off);
    }
    if (tx == 0) {
        atomicAdd(&o1[k0 + ty], p1);
        atomicAdd(&o2[k0 + ty], p2);
    }
    __syncthreads();
    float x = t[tx][ty];
    __nv_bfloat16 hb, lb;
    split1(x, &hb, &lb);
    size_t o = (size_t)(n0 + ty) * K + k0 + tx;
    hiT[o] = hb;
    loT[o] = lb;
}

/* ---- layer-1 dots: s[i] = x[i,:].ws1, d[i] = x[i,:].wd1 ----------------- */
__global__ void xdots(const float* __restrict__ x)
{
    int i = (blockIdx.x * blockDim.x + threadIdx.x) >> 5;
    int lane = threadIdx.x & 31;
    if (i >= NN) return;
    const float* row = x + (size_t)i * K0;
    float ss = 0.f, dd = 0.f;
    #pragma unroll
    for (int k = lane * 4; k < K0; k += 128) {
        float4 v = *(const float4*)&row[k];
        float4 a = *(const float4*)&g_ws1[k];
        float4 b = *(const float4*)&g_wd1[k];
        ss += v.x * a.x + v.y * a.y + v.z * a.z + v.w * a.w;
        dd += v.x * b.x + v.y * b.y + v.z * b.z + v.w * b.w;
    }
    #pragma unroll
    for (int off = 16; off > 0; off >>= 1) {
        ss += __shfl_xor_sync(0xffffffffu, ss, off);
        dd += __shfl_xor_sync(0xffffffffu, dd, off);
    }
    if (lane == 0) { g_s[i] = ss; g_d[i] = dd; }
}

/* ================= GEMM: C = A @ B, A/B pre-split bf16 =================== */
/* A: hi/lo [M][K]; B: hi/lo [N][K]. CTA tile 128x256, K chunk 64, 2 stages, */
/* cp.async staging. Optional split-K via blockIdx.z (atomicAdd into C).     */
#define STG_SZ (96 * 1024)
#define GEMM_SMEM (1024 + 2 * STG_SZ)

__global__ __launch_bounds__(256, 1)
void gemm_tc(const __nv_bfloat16* __restrict__ Ahi,
             const __nv_bfloat16* __restrict__ Alo,
             const __nv_bfloat16* __restrict__ BhiT,
             const __nv_bfloat16* __restrict__ BloT,
             float* __restrict__ C,
             __nv_bfloat16* __restrict__ ohi, __nv_bfloat16* __restrict__ olo,
             const float* __restrict__ bias,
             const float* __restrict__ ws, const float* __restrict__ wd,
             float* __restrict__ gs, float* __restrict__ gd,
             int M, int N, int K)
{
#if TC_OK
    extern __shared__ char smem[];
    const uint32_t sb = smem_u32(smem);
    const int tid = threadIdx.x, wid = tid >> 5, lane = tid & 31;
    const int bm = blockIdx.y * 128, bn = blockIdx.x * 256;
    const int Kc = K / gridDim.z;            /* split-K range per CTA */
    const int kbase = blockIdx.z * Kc;
    const int NC = Kc >> 6;
    const uint32_t IDESC = (1u << 4) | (1u << 7) | (1u << 10) | (32u << 17) | (8u << 24);

    if (wid == 0)
        asm volatile("tcgen05.alloc.cta_group::1.sync.aligned.shared::cta.b32 [%0], %1;"
                     :: "r"(sb), "r"(256u) : "memory");
    if (tid == 0) { MBAR_INIT(sb + 16, 1); MBAR_INIT(sb + 24, 1); }
    __syncthreads();
    uint32_t tmem;
    asm volatile("ld.shared.b32 %0, [%1];" : "=r"(tmem) : "r"(sb));

    const int arow = tid >> 1, ahalf = tid & 1;
    const int brow0 = tid >> 2, bquad = tid & 3;
    int rowA = bm + arow; if (rowA >= M) rowA = M - 1;
    int ph[2] = {0, 0};

    #define LOAD_CHUNK(k0, st) do {                                              \
        uint32_t s = sb + 1024 + (st) * STG_SZ;                                   \
        const __nv_bfloat16* aph = Ahi + (size_t)rowA * K + (k0) + ahalf * 32;    \
        const __nv_bfloat16* apl = Alo + (size_t)rowA * K + (k0) + ahalf * 32;    \
        _Pragma("unroll")                                                         \
        for (int g = 0; g < 4; g++) {                                             \
            uint32_t off = SWZ((uint32_t)(arow * 128 + (ahalf * 32 + g * 8) * 2));\
            CP16(s + off,         aph + g * 8);                                   \
            CP16(s + 16384 + off, apl + g * 8);                                   \
        }                                                                         \
        _Pragma("unroll")                                                         \
        for (int p = 0; p < 4; p++) {                                             \
            int br = brow0 + p * 64;                                              \
            size_t go = (size_t)(bn + br) * K + (k0) + bquad * 16;                \
            _Pragma("unroll")                                                     \
            for (int j = 0; j < 2; j++) {                                         \
                uint32_t off = SWZ((uint32_t)(br * 128 + bquad * 32 + j * 16));   \
                CP16(s + 32768 + off, BhiT + go + j * 8);                         \
                CP16(s + 65536 + off, BloT + go + j * 8);                         \
            }                                                                     \
        }                                                                         \
        CP_COMMIT(); } while (0)

    LOAD_CHUNK(kbase, 0);
    CP_WAIT0();
    FENCE_ASYNC();
    __syncthreads();

    for (int c = 0; c < NC; c++) {
        int st = c & 1;
        if (wid == 0) {
            uint32_t sbase = sb + 1024 + st * STG_SZ;
            uint64_t adh = mk_desc(sbase), adl = mk_desc(sbase + 16384);
            uint64_t bdh = mk_desc(sbase + 32768), bdl = mk_desc(sbase + 65536);
            if (elect1()) {
                #pragma unroll
                for (int ks = 0; ks < 4; ks++) {
                    mma_f16_ss(tmem, adh + ks * 2, bdh + ks * 2, IDESC, !(c == 0 && ks == 0));
                    mma_f16_ss(tmem, adh + ks * 2, bdl + ks * 2, IDESC, true);
                    mma_f16_ss(tmem, adl + ks * 2, bdh + ks * 2, IDESC, true);
                }
                TC_COMMIT(sb + 16 + 8 * st);
            }
        }
        if (c + 1 < NC) {
            int st2 = (c + 1) & 1;
            if (c >= 1) { MBAR_WAIT(sb + 16 + 8 * st2, ph[st2]); ph[st2] ^= 1; }
            LOAD_CHUNK(kbase + (c + 1) * 64, st2);
            CP_WAIT0();
            FENCE_ASYNC();
            __syncthreads();
        }
    }
    {
        int st = (NC - 1) & 1;
        MBAR_WAIT(sb + 16 + 8 * st, ph[st]);
        ph[st] ^= 1;
    }
    TC_FENCE_AFTER();

    /* ---- epilogue phase 1: TMEM -> swizzled SMEM ---- */
    if (wid < 4) {
        int row = wid * 32 + lane;
        #pragma unroll
        for (int nb = 0; nb < 8; nb++) {
            uint32_t r[32];
            LDTM_X32(r, tmem + nb * 32);
            TC_WAIT_LD();
            #pragma unroll
            for (int j = 0; j < 8; j++) {
                int c4 = nb * 8 + j;
                int pc4 = c4 ^ (row & 31);
                uint32_t addr = sb + 1024 + row * 1024 + pc4 * 16;
                asm volatile("st.shared.v4.b32 [%0], {%1,%2,%3,%4};"
                             :: "r"(addr), "r"(r[j*4]), "r"(r[j*4+1]),
                                "r"(r[j*4+2]), "r"(r[j*4+3]));
            }
        }
    }
    __syncthreads();

    /* ---- epilogue phase 2 ---- */
    if (ohi) {
        #pragma unroll
        for (int i = 0; i < 16; i++) {
            int row = wid * 16 + i;
            int grow = bm + row;
            if (grow >= M) continue;
            float ss = 0.f, dd = 0.f;
            #pragma unroll
            for (int hh = 0; hh < 2; hh++) {
                int c4 = hh * 32 + lane;
                int pc4 = c4 ^ (row & 31);
                float4 v = *(float4*)(smem + 1024 + row * 1024 + pc4 * 16);
                int c = bn + c4 * 4;
                float4 bb = *(const float4*)&bias[c];
                v.x = fmaxf(v.x + bb.x, 0.f); v.y = fmaxf(v.y + bb.y, 0.f);
                v.z = fmaxf(v.z + bb.z, 0.f); v.w = fmaxf(v.w + bb.w, 0.f);
                float4 wsv = *(const float4*)&ws[c];
                float4 wdv = *(const float4*)&wd[c];
                ss += v.x * wsv.x + v.y * wsv.y + v.z * wsv.z + v.w * wsv.w;
                dd += v.x * wdv.x + v.y * wdv.y + v.z * wdv.z + v.w * wdv.w;
                __nv_bfloat16 hb[4], lb[4];
                split1(v.x, &hb[0], &lb[0]); split1(v.y, &hb[1], &lb[1]);
                split1(v.z, &hb[2], &lb[2]); split1(v.w, &hb[3], &lb[3]);
                *(uint2*)&ohi[(size_t)grow * N + c] = *(uint2*)hb;
                *(uint2*)&olo[(size_t)grow * N + c] = *(uint2*)lb;
            }
            #pragma unroll
            for (int off = 16; off > 0; off >>= 1) {
                ss += __shfl_xor_sync(0xffffffffu, ss, off);
                dd += __shfl_xor_sync(0xffffffffu, dd, off);
            }
            if (lane == 0) {
                atomicAdd(&gs[grow], ss);
                atomicAdd(&gd[grow], dd);
            }
        }
    } else if (gridDim.z > 1) {
        #pragma unroll
        for (int i = 0; i < 16; i++) {
            int row = wid * 16 + i;
            int grow = bm + row;
            if (grow < M) {
                #pragma unroll
                for (int hh = 0; hh < 2; hh++) {
                    int c4 = hh * 32 + lane;
                    int pc4 = c4 ^ (row & 31);
                    float4 v = *(float4*)(smem + 1024 + row * 1024 + pc4 * 16);
                    float* cp = &C[(size_t)grow * N + bn + c4 * 4];
                    atomicAdd(cp + 0, v.x);
                    atomicAdd(cp + 1, v.y);
                    atomicAdd(cp + 2, v.z);
                    atomicAdd(cp + 3, v.w);
                }
            }
        }
    } else {
        #pragma unroll
        for (int i = 0; i < 16; i++) {
            int row = wid * 16 + i;
            int grow = bm + row;
            if (grow < M) {
                #pragma unroll
                for (int hh = 0; hh < 2; hh++) {
                    int c4 = hh * 32 + lane;
                    int pc4 = c4 ^ (row & 31);
                    uint4 v = *(uint4*)(smem + 1024 + row * 1024 + pc4 * 16);
                    *(uint4*)&C[(size_t)grow * N + bn + c4 * 4] = v;
                }
            }
        }
    }
    __syncthreads();
    if (wid == 0)
        asm volatile("tcgen05.dealloc.cta_group::1.sync.aligned.b32 %0, %1;"
                     :: "r"(tmem), "r"(256u));
#else
    /* ---------- SIMT fallback (generic pass; not selected on GB300) ------ */
    __shared__ float As[8][128];
    __shared__ float Bs[8][128];
    int tid = threadIdx.x;
    int bm = blockIdx.y * 128, bn0 = blockIdx.x * 256;
    int Kc = K / gridDim.z;
    int kbase = blockIdx.z * Kc;
    int arow = tid >> 1, acol = (tid & 1) * 4;
    int brow = tid >> 5, bcol = (tid & 31) * 4;
    int tx = tid & 15, ty = tid >> 4;

    for (int half = 0; half < 2; half++) {
        int bn = bn0 + half * 128;
        float acc[8][8];
        #pragma unroll
        for (int i = 0; i < 8; i++)
            #pragma unroll
            for (int j = 0; j < 8; j++) acc[i][j] = 0.f;

        for (int k0 = kbase; k0 < kbase + Kc; k0 += 8) {
            #pragma unroll
            for (int q = 0; q < 4; q++) {
                float v = 0.f;
                if (bm + arow < M) {
                    size_t o = (size_t)(bm + arow) * K + k0 + acol + q;
                    v = __bfloat162float(Ahi[o]) + __bfloat162float(Alo[o]);
                }
                As[acol + q][arow] = v;
            }
            #pragma unroll
            for (int j = 0; j < 4; j++) {
                size_t o = (size_t)(bn + bcol + j) * K + k0 + brow;
                Bs[brow][bcol + j] = __bfloat162float(BhiT[o]) + __bfloat162float(BloT[o]);
            }
            __syncthreads();
            #pragma unroll
            for (int k = 0; k < 8; k++) {
                float a_frag[8], b_frag[8];
                *(float4*)&a_frag[0] = *(const float4*)&As[k][ty * 8];
                *(float4*)&a_frag[4] = *(const float4*)&As[k][ty * 8 + 4];
                *(float4*)&b_frag[0] = *(const float4*)&Bs[k][tx * 8];
                *(float4*)&b_frag[4] = *(const float4*)&Bs[k][tx * 8 + 4];
                #pragma unroll
                for (int i = 0; i < 8; i++)
                    #pragma unroll
                    for (int j = 0; j < 8; j++)
                        acc[i][j] += a_frag[i] * b_frag[j];
            }
            __syncthreads();
        }
        #pragma unroll
        for (int i = 0; i < 8; i++) {
            int row = bm + ty * 8 + i;
            if (row >= M) continue;
            if (ohi) {
                float ss = 0.f, dd = 0.f;
                #pragma unroll
                for (int j = 0; j < 8; j++) {
                    int c = bn + tx * 8 + j;
                    float v = fmaxf(acc[i][j] + bias[c], 0.f);
                    ss += v * ws[c];
                    dd += v * wd[c];
                    __nv_bfloat16 hb, lb;
                    split1(v, &hb, &lb);
                    ohi[(size_t)row * N + c] = hb;
                    olo[(size_t)row * N + c] = lb;
                }
                atomicAdd(&gs[row], ss);
                atomicAdd(&gd[row], dd);
            } else if (gridDim.z > 1) {
                #pragma unroll
                for (int j = 0; j < 8; j++)
                    atomicAdd(&C[(size_t)row * N + bn + tx * 8 + j], acc[i][j]);
            } else {
                #pragma unroll
                for (int j = 0; j < 8; j += 4) {
                    float4 v = make_float4(acc[i][j], acc[i][j+1], acc[i][j+2], acc[i][j+3]);
                    *(float4*)&C[(size_t)row * N + bn + tx * 8 + j] = v;
                }
            }
        }
        __syncthreads();
    }
#endif
}

/* ---------------- small utility kernels ---------------------------------- */
__global__ void k_zero2_i(int* a, int* b, int n) {
    int i = blockIdx.x * blockDim.x + threadIdx.x;
    if (i < n) { a[i] = 0; b[i] = 0; }
}
__global__ void k_zero2_f(float* a, float* b, int n) {
    int i = blockIdx.x * blockDim.x + threadIdx.x;
    if (i < n) { a[i] = 0.f; b[i] = 0.f; }
}
__global__ void k_zerof(float* a, size_t n) {
    size_t i = (size_t)blockIdx.x * blockDim.x + threadIdx.x;
    size_t i4 = i * 4;
    if (i4 + 3 < n) *(float4*)&a[i4] = make_float4(0.f, 0.f, 0.f, 0.f);
}
__global__ void k_zero_dots() {   /* zero ws1/wd1 (K0) and ws2/wd2 (F1) */
    int i = blockIdx.x * blockDim.x + threadIdx.x;
    if (i < K0) { g_ws1[i] = 0.f; g_wd1[i] = 0.f; }
    if (i < F1) { g_ws2[i] = 0.f; g_wd2[i] = 0.f; }
}

/* ---------------- CSR build (by dst) -------------------------------------- */
__global__ void k_hist(const int* __restrict__ ei) {
    int e = blockIdx.x * blockDim.x + threadIdx.x;
    if (e >= MT) return;
    int dst = (e < NE) ? ei[NE + e] : (e - NE);
    atomicAdd(&g_deg[dst], 1);
}

__global__ void k_scan() {
    __shared__ int sh[1024];
    __shared__ int carry;
    int t = threadIdx.x;
    if (t == 0) { carry = 0; g_rowptr[0] = 0; }
    __syncthreads();
    for (int base = 0; base < NN; base += 1024) {
        int i = base + t;
        int v = (i < NN) ? g_deg[i] : 0;
        sh[t] = v;
        __syncthreads();
        #pragma unroll
        for (int off = 1; off < 1024; off <<= 1) {
            int add = (t >= off) ? sh[t - off] : 0;
            __syncthreads();
            sh[t] += add;
            __syncthreads();
        }
        int c = carry;
        if (i < NN) g_rowptr[i + 1] = sh[t] + c;
        __syncthreads();
        if (t == 0) carry = c + sh[1023];
        __syncthreads();
    }
}

__global__ void k_scatter(const int* __restrict__ ei) {
    int e = blockIdx.x * blockDim.x + threadIdx.x;
    if (e >= MT) return;
    int src, dst;
    if (e < NE) { src = ei[e]; dst = ei[NE + e]; }
    else        { src = e - NE; dst = e - NE; }
    int pos = g_rowptr[dst] + atomicAdd(&g_cursor[dst], 1);
    g_csrc[pos] = src;
}

/* ---- block-level softmax prep: returns (m, inv_sum) for node j ----------- */
/* NT = blockDim; red[] must have >= NT/32 floats                             */
template <int NT>
__device__ __forceinline__ void node_softmax(int beg, int end, float dd,
                                             float* red, float* out_m, float* out_inv)
{
    int t = threadIdx.x, wid = t >> 5, lane = t & 31;
    const int NW = NT / 32;
    float m = -1e30f;
    for (int p = beg + t; p < end; p += NT)
        m = fmaxf(m, lrelu(g_s[g_csrc[p]] + dd));
    #pragma unroll
    for (int off = 16; off > 0; off >>= 1)
        m = fmaxf(m, __shfl_xor_sync(0xffffffffu, m, off));
    if (lane == 0) red[wid] = m;
    __syncthreads();
    m = red[0];
    #pragma unroll
    for (int w = 1; w < NW; w++) m = fmaxf(m, red[w]);
    __syncthreads();
    float sum = 0.f;
    for (int p = beg + t; p < end; p += NT)
        sum += expf(lrelu(g_s[g_csrc[p]] + dd) - m);
    #pragma unroll
    for (int off = 16; off > 0; off >>= 1)
        sum += __shfl_xor_sync(0xffffffffu, sum, off);
    if (lane == 0) red[wid] = sum;
    __syncthreads();
    sum = 0.f;
    #pragma unroll
    for (int w = 0; w < NW; w++) sum += red[w];
    __syncthreads();
    *out_m = m;
    *out_inv = 1.f / sum;
}

/* ---------------- aggregate x (512-dim) w/ fused softmax ------------------- */
__global__ __launch_bounds__(128)
void aggregate512(const float* __restrict__ x)
{
    __shared__ float sal[128];
    __shared__ int   ssr[128];
    __shared__ float red[4];
    int j = blockIdx.x;
    int t = threadIdx.x;
    int beg = g_rowptr[j], end = g_rowptr[j + 1];
    int deg = end - beg;
    float dd = g_d[j];
    float m, inv;
    node_softmax<128>(beg, end, dd, red, &m, &inv);

    float4 acc = make_float4(0.f, 0.f, 0.f, 0.f);
    for (int base = 0; base < deg; base += 128) {
        int n = deg - base; if (n > 128) n = 128;
        if (t < n) {
            int s = g_csrc[beg + base + t];
            ssr[t] = s;
            sal[t] = expf(lrelu(g_s[s] + dd) - m) * inv;
        }
        __syncthreads();
        #pragma unroll 4
        for (int p = 0; p < n; p++) {
            float al = sal[p];
            float4 v = *(const float4*)(x + (size_t)ssr[p] * K0 + t * 4);
            acc.x += al * v.x; acc.y += al * v.y;
            acc.z += al * v.z; acc.w += al * v.w;
        }
        __syncthreads();
    }
    __nv_bfloat16 hb[4], lb[4];
    split1(acc.x, &hb[0], &lb[0]); split1(acc.y, &hb[1], &lb[1]);
    split1(acc.z, &hb[2], &lb[2]); split1(acc.w, &hb[3], &lb[3]);
    *(uint2*)&g_xahi[(size_t)j * K0 + t * 4] = *(uint2*)hb;
    *(uint2*)&g_xalo[(size_t)j * K0 + t * 4] = *(uint2*)lb;
}

/* ---------------- aggregate, F=1024, fused softmax, emits fp32 ------------- */
__global__ __launch_bounds__(256)
void aggregate1024(const float* __restrict__ h, const float* __restrict__ bias,
                   float* __restrict__ out)
{
    __shared__ float sal[128];
    __shared__ int   ssr[128];
    __shared__ float red[8];
    int j = blockIdx.x;
    int t = threadIdx.x;
    int beg = g_rowptr[j], end = g_rowptr[j + 1];
    int deg = end - beg;
    float dd = g_d[j];
    float m, inv;
    node_softmax<256>(beg, end, dd, red, &m, &inv);

    float4 acc = make_float4(0.f, 0.f, 0.f, 0.f);
    for (int base = 0; base < deg; base += 128) {
        int n = deg - base; if (n > 128) n = 128;
        if (t < 128 && t < n) {
            int s = g_csrc[beg + base + t];
            ssr[t] = s;
            sal[t] = expf(lrelu(g_s[s] + dd) - m) * inv;
        }
        __syncthreads();
        #pragma unroll 4
        for (int p = 0; p < n; p++) {
            float al = sal[p];
            float4 v = *(const float4*)(h + (size_t)ssr[p] * F2 + t * 4);
            acc.x += al * v.x; acc.y += al * v.y;
            acc.z += al * v.z; acc.w += al * v.w;
        }
        __syncthreads();
    }
    int c = t * 4;
    float4 bb = *(const float4*)&bias[c];
    float4 v;
    v.x = fmaxf(acc.x + bb.x, 0.f);
    v.y = fmaxf(acc.y + bb.y, 0.f);
    v.z = fmaxf(acc.z + bb.z, 0.f);
    v.w = fmaxf(acc.w + bb.w, 0.f);
    *(float4*)&out[(size_t)j * F2 + c] = v;
}

/* ---- aggregate F=7 w/ inline softmax + log_softmax (fused) --------------- */
__global__ void aggregate3_ls(const float* __restrict__ h, const float* __restrict__ bias,
                              float* __restrict__ out) {
    int j = blockIdx.x * blockDim.x + threadIdx.x;
    if (j >= NN) return;
    int beg = g_rowptr[j], end = g_rowptr[j + 1];
    float dd = g_d[j];
    float m = -1e30f;
    for (int p = beg; p < end; p++)
        m = fmaxf(m, lrelu(g_s[g_csrc[p]] + dd));
    float sum = 0.f;
    for (int p = beg; p < end; p++)
        sum += expf(lrelu(g_s[g_csrc[p]] + dd) - m);
    float inv = 1.f / sum;

    float acc[F3];
    #pragma unroll
    for (int c = 0; c < F3; c++) acc[c] = 0.f;
    for (int p = beg; p < end; p++) {
        int src = g_csrc[p];
        float al = expf(lrelu(g_s[src] + dd) - m) * inv;
        #pragma unroll
        for (int c = 0; c < F3; c++) acc[c] += al * h[src * F3 + c];
    }
    float mm = -1e30f;
    #pragma unroll
    for (int c = 0; c < F3; c++) { acc[c] += bias[c]; mm = fmaxf(mm, acc[c]); }
    float s = 0.f;
    #pragma unroll
    for (int c = 0; c < F3; c++) s += expf(acc[c] - mm);
    float l = logf(s) + mm;
    #pragma unroll
    for (int c = 0; c < F3; c++) out[j * F3 + c] = acc[c] - l;
}

/* ---------------- layer 3 GEMM (N=7) with fused dots ----------------------- */
__global__ void gemm3(const float* __restrict__ A, const float* __restrict__ W,
                      float* __restrict__ C,
                      const float* __restrict__ asrc, const float* __restrict__ adst)
{
    int w = (blockIdx.x * blockDim.x + threadIdx.x) >> 5;
    int lane = threadIdx.x & 31;
    if (w >= NN) return;
    float acc[F3];
    #pragma unroll
    for (int c = 0; c < F3; c++) acc[c] = 0.f;
    for (int k = lane; k < F2; k += 32) {
        float a = A[(size_t)w * F2 + k];
        #pragma unroll
        for (int c = 0; c < F3; c++) acc[c] += a * W[k * F3 + c];
    }
    #pragma unroll
    for (int c = 0; c < F3; c++) {
        #pragma unroll
        for (int off = 16; off > 0; off >>= 1)
            acc[c] += __shfl_xor_sync(0xffffffffu, acc[c], off);
    }
    if (lane == 0) {
        float ss = 0.f, dd = 0.f;
        #pragma unroll
        for (int c = 0; c < F3; c++) {
            C[w * F3 + c] = acc[c];
            ss += acc[c] * asrc[c];
            dd += acc[c] * adst[c];
        }
        g_s[w] = ss;
        g_d[w] = dd;
    }
}

/* ---------------- launch --------------------------------------------------- */
extern "C" void kernel_launch(void* const* d_in, const int* in_sizes, int n_in,
                              void* d_out, int out_size)
{
    const float* x   = (const float*)d_in[0];
    const int*   ei  = (const int*)d_in[1];
    const float* W1  = (const float*)d_in[2];
    const float* as1 = (const float*)d_in[3];
    const float* ad1 = (const float*)d_in[4];
    const float* b1  = (const float*)d_in[5];
    const float* W2  = (const float*)d_in[6];
    const float* as2 = (const float*)d_in[7];
    const float* ad2 = (const float*)d_in[8];
    const float* b2  = (const float*)d_in[9];
    const float* W3  = (const float*)d_in[10];
    const float* as3 = (const float*)d_in[11];
    const float* ad3 = (const float*)d_in[12];
    const float* b3  = (const float*)d_in[13];
    float* out = (float*)d_out;

    float *h2, *o2, *h3, *gs, *gd, *ws1, *wd1, *ws2, *wd2;
    int *deg, *cur;
    __nv_bfloat16 *w1h, *w1l, *w2h, *w2l, *xah, *xal, *a1h, *a1l;
    cudaGetSymbolAddress((void**)&h2,  g_h2);
    cudaGetSymbolAddress((void**)&o2,  g_o2);
    cudaGetSymbolAddress((void**)&h3,  g_h3);
    cudaGetSymbolAddress((void**)&gs,  g_s);
    cudaGetSymbolAddress((void**)&gd,  g_d);
    cudaGetSymbolAddress((void**)&ws1, g_ws1);
    cudaGetSymbolAddress((void**)&wd1, g_wd1);
    cudaGetSymbolAddress((void**)&ws2, g_ws2);
    cudaGetSymbolAddress((void**)&wd2, g_wd2);
    cudaGetSymbolAddress((void**)&deg, g_deg);
    cudaGetSymbolAddress((void**)&cur, g_cursor);
    cudaGetSymbolAddress((void**)&w1h, g_w1hi);
    cudaGetSymbolAddress((void**)&w1l, g_w1lo);
    cudaGetSymbolAddress((void**)&w2h, g_w2hi);
    cudaGetSymbolAddress((void**)&w2l, g_w2lo);
    cudaGetSymbolAddress((void**)&xah, g_xahi);
    cudaGetSymbolAddress((void**)&xal, g_xalo);
    cudaGetSymbolAddress((void**)&a1h, g_a1hi);
    cudaGetSymbolAddress((void**)&a1l, g_a1lo);

    cudaFuncSetAttribute(gemm_tc, cudaFuncAttributeMaxDynamicSharedMemorySize, GEMM_SMEM);

    const int TB = 256;
    int egrid = (MT + TB - 1) / TB;
    int ngrid = (NN + TB - 1) / TB;
    int wgrid = (NN * 32 + TB - 1) / TB;
    int mblk = (NN + 127) / 128;

    /* ---- prep: weight split (w/ fused MV dots), CSR build ---- */
    k_zero_dots<<<(F1 + TB - 1) / TB, TB>>>();
    tsplit<<<dim3(F1 / 32, K0 / 32), dim3(32, 32)>>>(W1, w1h, w1l, as1, ad1, ws1, wd1, K0, F1);
    tsplit<<<dim3(F2 / 32, F1 / 32), dim3(32, 32)>>>(W2, w2h, w2l, as2, ad2, ws2, wd2, F1, F2);
    xdots<<<wgrid, TB>>>(x);
    k_zero2_i<<<ngrid, TB>>>(deg, cur, NN);
    k_hist<<<egrid, TB>>>(ei);
    k_scan<<<1, 1024>>>();
    k_scatter<<<egrid, TB>>>(ei);

    /* ---- layer 1: aggregate x (fused softmax), GEMM w/ fused epilogue ---- */
    aggregate512<<<NN, 128>>>(x);
    k_zero2_f<<<ngrid, TB>>>(gs, gd, NN);
    gemm_tc<<<dim3(F1 / 256, mblk, 1), 256, GEMM_SMEM>>>(
        xah, xal, w1h, w1l, (float*)0, a1h, a1l, b1, ws2, wd2, gs, gd, NN, F1, K0);

    /* ---- layer 2: split-K=2 GEMM (atomicAdd into zeroed h2) ---- */
    k_zerof<<<((size_t)NN * F2 / 4 + TB - 1) / TB, TB>>>(h2, (size_t)NN * F2);
    gemm_tc<<<dim3(F2 / 256, mblk, 2), 256, GEMM_SMEM>>>(
        a1h, a1l, w2h, w2l, h2, (__nv_bfloat16*)0, (__nv_bfloat16*)0,
        (float*)0, (float*)0, (float*)0, (float*)0, (float*)0, NN, F2, F1);
    aggregate1024<<<NN, 256>>>(h2, b2, o2);

    /* ---- layer 3 ---- */
    gemm3<<<wgrid, TB>>>(o2, W3, h3, as3, ad3);
    aggregate3_ls<<<ngrid, TB>>>(h3, b3, out);
}

// round 17
// speedup vs baseline: 1.0167x; 1.0167x over previous
#include <cuda_runtime.h>
#include <cuda_bf16.h>
#include <stdint.h>
#include <math.h>

#define NN 10000
#define NE 80000
#define MT (NE + NN)          /* 90000 edges incl. self loops */
#define K0 512
#define F1 4096
#define F2 1024
#define F3 7

#if defined(__CUDA_ARCH__) && defined(__CUDA_ARCH_FEAT_SM103_ALL)
#define TC_OK 1
#else
#define TC_OK 0
#endif

/* ---------------- scratch (device globals; no allocations allowed) -------- */
__device__ float g_h2[NN * (size_t)F2];
__device__ float g_o2[NN * (size_t)F2];
__device__ float g_h3[NN * F3];
__device__ float g_s[NN];
__device__ float g_d[NN];
__device__ float g_alpha[MT];
__device__ float g_ws1[K0];
__device__ float g_wd1[K0];
__device__ float g_ws2[F1];
__device__ float g_wd2[F1];
__device__ int   g_deg[NN];
__device__ int   g_rowptr[NN + 1];
__device__ int   g_cursor[NN];
__device__ int   g_csrc[MT];
/* pre-split operands (bf16) */
__device__ __nv_bfloat16 g_xahi[(size_t)NN * K0];   /* aggregated x, split */
__device__ __nv_bfloat16 g_xalo[(size_t)NN * K0];
__device__ __nv_bfloat16 g_a1hi[(size_t)NN * F1];   /* o1 split */
__device__ __nv_bfloat16 g_a1lo[(size_t)NN * F1];
__device__ __nv_bfloat16 g_w1hi[(size_t)F1 * K0];
__device__ __nv_bfloat16 g_w1lo[(size_t)F1 * K0];
__device__ __nv_bfloat16 g_w2hi[(size_t)F2 * F1];
__device__ __nv_bfloat16 g_w2lo[(size_t)F2 * F1];

/* ================= tcgen05 helpers (inline PTX) ========================== */
__device__ __forceinline__ uint32_t smem_u32(const void* p) {
    uint32_t a;
    asm("{ .reg .u64 t; cvta.to.shared.u64 t, %1; cvt.u32.u64 %0, t; }"
        : "=r"(a) : "l"(p));
    return a;
}
#if TC_OK
__device__ __forceinline__ uint32_t elect1() {
    uint32_t r;
    asm volatile("{ .reg .pred p; elect.sync _|p, 0xFFFFFFFF; selp.b32 %0,1,0,p; }"
                 : "=r"(r));
    return r;
}
__device__ __forceinline__ void mma_f16_ss(uint32_t d, uint64_t ad, uint64_t bd,
                                           uint32_t idesc, bool accum) {
    uint32_t en = accum ? 1u : 0u;
    asm volatile(
        "{\n\t.reg .pred p;\n\tsetp.ne.u32 p, %5, 0;\n\t"
        "tcgen05.mma.cta_group::1.kind::f16 [%0], %1, %2, %3, {%4,%4,%4,%4}, p;\n\t}"
        :: "r"(d), "l"(ad), "l"(bd), "r"(idesc), "r"(0u), "r"(en) : "memory");
}
#define TC_COMMIT(mbar) \
    asm volatile("tcgen05.commit.cta_group::1.mbarrier::arrive::one.shared::cluster.b64 [%0];" \
                 :: "r"((uint32_t)(mbar)) : "memory")
#define MBAR_INIT(a, c) \
    asm volatile("mbarrier.init.shared.b64 [%0], %1;" :: "r"((uint32_t)(a)), "r"((uint32_t)(c)) : "memory")
#define MBAR_WAIT(a, ph) do { \
    uint32_t _m = (uint32_t)(a); uint32_t _p = (uint32_t)(ph); uint32_t _done; \
    asm volatile("{\n\t.reg .pred p;\n\t" \
        "mbarrier.try_wait.parity.acquire.cta.shared::cta.b64 p, [%1], %2;\n\t" \
        "selp.b32 %0, 1, 0, p;\n\t}" : "=r"(_done) : "r"(_m), "r"(_p) : "memory"); \
    if (!_done) { \
        asm volatile("{\n\t.reg .pred P1;\n\t" \
            "WL_%=:\n\t" \
            "mbarrier.try_wait.parity.acquire.cta.shared::cta.b64 P1, [%0], %1, 0x989680;\n\t" \
            "@P1 bra.uni WD_%=;\n\t" \
            "bra.uni WL_%=;\n\t" \
            "WD_%=:\n\t}" :: "r"(_m), "r"(_p) : "memory"); \
    } } while (0)
#define LDTM_X32(r, a) \
    asm volatile("tcgen05.ld.sync.aligned.32x32b.x32.b32 " \
        "{%0,%1,%2,%3,%4,%5,%6,%7,%8,%9,%10,%11,%12,%13,%14,%15," \
        "%16,%17,%18,%19,%20,%21,%22,%23,%24,%25,%26,%27,%28,%29,%30,%31}, [%32];" \
        : "=r"((r)[0]),"=r"((r)[1]),"=r"((r)[2]),"=r"((r)[3]),"=r"((r)[4]),"=r"((r)[5]),"=r"((r)[6]),"=r"((r)[7]), \
          "=r"((r)[8]),"=r"((r)[9]),"=r"((r)[10]),"=r"((r)[11]),"=r"((r)[12]),"=r"((r)[13]),"=r"((r)[14]),"=r"((r)[15]), \
          "=r"((r)[16]),"=r"((r)[17]),"=r"((r)[18]),"=r"((r)[19]),"=r"((r)[20]),"=r"((r)[21]),"=r"((r)[22]),"=r"((r)[23]), \
          "=r"((r)[24]),"=r"((r)[25]),"=r"((r)[26]),"=r"((r)[27]),"=r"((r)[28]),"=r"((r)[29]),"=r"((r)[30]),"=r"((r)[31]) \
        : "r"(a))
#define TC_WAIT_LD()  asm volatile("tcgen05.wait::ld.sync.aligned;" ::: "memory")
#define TC_FENCE_AFTER() asm volatile("tcgen05.fence::after_thread_sync;" ::: "memory")
#define FENCE_ASYNC() asm volatile("fence.proxy.async.shared::cta;" ::: "memory")
#define CP16(sa, ga) \
    asm volatile("cp.async.cg.shared.global [%0], [%1], 16;" \
                 :: "r"((uint32_t)(sa)), "l"(ga) : "memory")
#define CP_COMMIT() asm volatile("cp.async.commit_group;" ::: "memory")
#define CP_WAIT0()  asm volatile("cp.async.wait_group 0;" ::: "memory")
#endif /* TC_OK */
#define SWZ(x) ((x) ^ (((x) >> 3) & 0x70))

static constexpr unsigned long long DESC_BASE =
    (2ull << 61) | (1ull << 46) | (64ull << 32) | (1ull << 16);
__device__ __forceinline__ uint64_t mk_desc(uint32_t addr) {
    return DESC_BASE | ((uint64_t)(addr >> 4) & 0x3FFF);
}

/* ---- fp32 -> (hi, lo) bf16 ---- */
__device__ __forceinline__ void split1(float x, __nv_bfloat16* h, __nv_bfloat16* l) {
    __nv_bfloat16 hb = __float2bfloat16(x);
    *h = hb;
    *l = __float2bfloat16(x - __bfloat162float(hb));
}

/* ---- transpose + split weights: W[K][N] -> hiT/loT [N][K] bf16 ---------- */
__global__ void tsplit(const float* __restrict__ W, __nv_bfloat16* __restrict__ hiT,
                       __nv_bfloat16* __restrict__ loT, int K, int N)
{
    __shared__ float t[32][33];
    int n0 = blockIdx.x * 32, k0 = blockIdx.y * 32;
    int tx = threadIdx.x, ty = threadIdx.y;
    t[ty][tx] = W[(size_t)(k0 + ty) * N + n0 + tx];
    __syncthreads();
    float x = t[tx][ty];
    __nv_bfloat16 hb, lb;
    split1(x, &hb, &lb);
    size_t o = (size_t)(n0 + ty) * K + k0 + tx;
    hiT[o] = hb;
    loT[o] = lb;
}

/* ---- MV: out1[r] = W[r,:].v1, out2[r] = W[r,:].v2 (warp per row) -------- */
__global__ void mv_rows(const float* __restrict__ W,
                        const float* __restrict__ v1, const float* __restrict__ v2,
                        float* __restrict__ o1, float* __restrict__ o2, int K, int N)
{
    int r = (blockIdx.x * blockDim.x + threadIdx.x) >> 5;
    int lane = threadIdx.x & 31;
    if (r >= K) return;
    const float* row = W + (size_t)r * N;
    float s1 = 0.f, s2 = 0.f;
    for (int k = lane * 4; k < N; k += 128) {
        float4 w = *(const float4*)&row[k];
        float4 a = *(const float4*)&v1[k];
        float4 b = *(const float4*)&v2[k];
        s1 += w.x * a.x + w.y * a.y + w.z * a.z + w.w * a.w;
        s2 += w.x * b.x + w.y * b.y + w.z * b.z + w.w * b.w;
    }
    #pragma unroll
    for (int off = 16; off > 0; off >>= 1) {
        s1 += __shfl_xor_sync(0xffffffffu, s1, off);
        s2 += __shfl_xor_sync(0xffffffffu, s2, off);
    }
    if (lane == 0) { o1[r] = s1; o2[r] = s2; }
}

/* ---- layer-1 dots: s[i] = x[i,:].ws1, d[i] = x[i,:].wd1 ----------------- */
__global__ void xdots(const float* __restrict__ x)
{
    int i = (blockIdx.x * blockDim.x + threadIdx.x) >> 5;
    int lane = threadIdx.x & 31;
    if (i >= NN) return;
    const float* row = x + (size_t)i * K0;
    float ss = 0.f, dd = 0.f;
    #pragma unroll
    for (int k = lane * 4; k < K0; k += 128) {
        float4 v = *(const float4*)&row[k];
        float4 a = *(const float4*)&g_ws1[k];
        float4 b = *(const float4*)&g_wd1[k];
        ss += v.x * a.x + v.y * a.y + v.z * a.z + v.w * a.w;
        dd += v.x * b.x + v.y * b.y + v.z * b.z + v.w * b.w;
    }
    #pragma unroll
    for (int off = 16; off > 0; off >>= 1) {
        ss += __shfl_xor_sync(0xffffffffu, ss, off);
        dd += __shfl_xor_sync(0xffffffffu, dd, off);
    }
    if (lane == 0) { g_s[i] = ss; g_d[i] = dd; }
}

/* ================= GEMM: C = A @ B, A/B pre-split bf16 =================== */
/* A: hi/lo [M][K]; B: hi/lo [N][K]. CTA tile 128x256, K chunk 64, 2 stages, */
/* cp.async staging. Optional split-K via blockIdx.z (atomicAdd into C).     */
#define STG_SZ (96 * 1024)
#define GEMM_SMEM (1024 + 2 * STG_SZ)

__global__ __launch_bounds__(256, 1)
void gemm_tc(const __nv_bfloat16* __restrict__ Ahi,
             const __nv_bfloat16* __restrict__ Alo,
             const __nv_bfloat16* __restrict__ BhiT,
             const __nv_bfloat16* __restrict__ BloT,
             float* __restrict__ C,
             __nv_bfloat16* __restrict__ ohi, __nv_bfloat16* __restrict__ olo,
             const float* __restrict__ bias,
             const float* __restrict__ ws, const float* __restrict__ wd,
             float* __restrict__ gs, float* __restrict__ gd,
             int M, int N, int K)
{
#if TC_OK
    extern __shared__ char smem[];
    const uint32_t sb = smem_u32(smem);
    const int tid = threadIdx.x, wid = tid >> 5, lane = tid & 31;
    const int bm = blockIdx.y * 128, bn = blockIdx.x * 256;
    const int Kc = K / gridDim.z;            /* split-K range per CTA */
    const int kbase = blockIdx.z * Kc;
    const int NC = Kc >> 6;
    const uint32_t IDESC = (1u << 4) | (1u << 7) | (1u << 10) | (32u << 17) | (8u << 24);

    if (wid == 0)
        asm volatile("tcgen05.alloc.cta_group::1.sync.aligned.shared::cta.b32 [%0], %1;"
                     :: "r"(sb), "r"(256u) : "memory");
    if (tid == 0) { MBAR_INIT(sb + 16, 1); MBAR_INIT(sb + 24, 1); }
    __syncthreads();
    uint32_t tmem;
    asm volatile("ld.shared.b32 %0, [%1];" : "=r"(tmem) : "r"(sb));

    const int arow = tid >> 1, ahalf = tid & 1;
    const int brow0 = tid >> 2, bquad = tid & 3;
    int rowA = bm + arow; if (rowA >= M) rowA = M - 1;
    int ph[2] = {0, 0};

    #define LOAD_CHUNK(k0, st) do {                                              \
        uint32_t s = sb + 1024 + (st) * STG_SZ;                                   \
        const __nv_bfloat16* aph = Ahi + (size_t)rowA * K + (k0) + ahalf * 32;    \
        const __nv_bfloat16* apl = Alo + (size_t)rowA * K + (k0) + ahalf * 32;    \
        _Pragma("unroll")                                                         \
        for (int g = 0; g < 4; g++) {                                             \
            uint32_t off = SWZ((uint32_t)(arow * 128 + (ahalf * 32 + g * 8) * 2));\
            CP16(s + off,         aph + g * 8);                                   \
            CP16(s + 16384 + off, apl + g * 8);                                   \
        }                                                                         \
        _Pragma("unroll")                                                         \
        for (int p = 0; p < 4; p++) {                                             \
            int br = brow0 + p * 64;                                              \
            size_t go = (size_t)(bn + br) * K + (k0) + bquad * 16;                \
            _Pragma("unroll")                                                     \
            for (int j = 0; j < 2; j++) {                                         \
                uint32_t off = SWZ((uint32_t)(br * 128 + bquad * 32 + j * 16));   \
                CP16(s + 32768 + off, BhiT + go + j * 8);                         \
                CP16(s + 65536 + off, BloT + go + j * 8);                         \
            }                                                                     \
        }                                                                         \
        CP_COMMIT(); } while (0)

    LOAD_CHUNK(kbase, 0);
    CP_WAIT0();
    FENCE_ASYNC();
    __syncthreads();

    for (int c = 0; c < NC; c++) {
        int st = c & 1;
        if (wid == 0) {
            uint32_t sbase = sb + 1024 + st * STG_SZ;
            uint64_t adh = mk_desc(sbase), adl = mk_desc(sbase + 16384);
            uint64_t bdh = mk_desc(sbase + 32768), bdl = mk_desc(sbase + 65536);
            if (elect1()) {
                #pragma unroll
                for (int ks = 0; ks < 4; ks++) {
                    mma_f16_ss(tmem, adh + ks * 2, bdh + ks * 2, IDESC, !(c == 0 && ks == 0));
                    mma_f16_ss(tmem, adh + ks * 2, bdl + ks * 2, IDESC, true);
                    mma_f16_ss(tmem, adl + ks * 2, bdh + ks * 2, IDESC, true);
                }
                TC_COMMIT(sb + 16 + 8 * st);
            }
        }
        if (c + 1 < NC) {
            int st2 = (c + 1) & 1;
            if (c >= 1) { MBAR_WAIT(sb + 16 + 8 * st2, ph[st2]); ph[st2] ^= 1; }
            LOAD_CHUNK(kbase + (c + 1) * 64, st2);
            CP_WAIT0();
            FENCE_ASYNC();
            __syncthreads();
        }
    }
    {
        int st = (NC - 1) & 1;
        MBAR_WAIT(sb + 16 + 8 * st, ph[st]);
        ph[st] ^= 1;
    }
    TC_FENCE_AFTER();

    /* ---- epilogue phase 1: TMEM -> swizzled SMEM ---- */
    if (wid < 4) {
        int row = wid * 32 + lane;
        #pragma unroll
        for (int nb = 0; nb < 8; nb++) {
            uint32_t r[32];
            LDTM_X32(r, tmem + nb * 32);
            TC_WAIT_LD();
            #pragma unroll
            for (int j = 0; j < 8; j++) {
                int c4 = nb * 8 + j;
                int pc4 = c4 ^ (row & 31);
                uint32_t addr = sb + 1024 + row * 1024 + pc4 * 16;
                asm volatile("st.shared.v4.b32 [%0], {%1,%2,%3,%4};"
                             :: "r"(addr), "r"(r[j*4]), "r"(r[j*4+1]),
                                "r"(r[j*4+2]), "r"(r[j*4+3]));
            }
        }
    }
    __syncthreads();

    /* ---- epilogue phase 2 ---- */
    if (ohi) {
        #pragma unroll
        for (int i = 0; i < 16; i++) {
            int row = wid * 16 + i;
            int grow = bm + row;
            if (grow >= M) continue;
            float ss = 0.f, dd = 0.f;
            #pragma unroll
            for (int hh = 0; hh < 2; hh++) {
                int c4 = hh * 32 + lane;
                int pc4 = c4 ^ (row & 31);
                float4 v = *(float4*)(smem + 1024 + row * 1024 + pc4 * 16);
                int c = bn + c4 * 4;
                float4 bb = *(const float4*)&bias[c];
                v.x = fmaxf(v.x + bb.x, 0.f); v.y = fmaxf(v.y + bb.y, 0.f);
                v.z = fmaxf(v.z + bb.z, 0.f); v.w = fmaxf(v.w + bb.w, 0.f);
                float4 wsv = *(const float4*)&ws[c];
                float4 wdv = *(const float4*)&wd[c];
                ss += v.x * wsv.x + v.y * wsv.y + v.z * wsv.z + v.w * wsv.w;
                dd += v.x * wdv.x + v.y * wdv.y + v.z * wdv.z + v.w * wdv.w;
                __nv_bfloat16 hb[4], lb[4];
                split1(v.x, &hb[0], &lb[0]); split1(v.y, &hb[1], &lb[1]);
                split1(v.z, &hb[2], &lb[2]); split1(v.w, &hb[3], &lb[3]);
                *(uint2*)&ohi[(size_t)grow * N + c] = *(uint2*)hb;
                *(uint2*)&olo[(size_t)grow * N + c] = *(uint2*)lb;
            }
            #pragma unroll
            for (int off = 16; off > 0; off >>= 1) {
                ss += __shfl_xor_sync(0xffffffffu, ss, off);
                dd += __shfl_xor_sync(0xffffffffu, dd, off);
            }
            if (lane == 0) {
                atomicAdd(&gs[grow], ss);
                atomicAdd(&gd[grow], dd);
            }
        }
    } else if (gridDim.z > 1) {
        #pragma unroll
        for (int i = 0; i < 16; i++) {
            int row = wid * 16 + i;
            int grow = bm + row;
            if (grow < M) {
                #pragma unroll
                for (int hh = 0; hh < 2; hh++) {
                    int c4 = hh * 32 + lane;
                    int pc4 = c4 ^ (row & 31);
                    float4 v = *(float4*)(smem + 1024 + row * 1024 + pc4 * 16);
                    float* cp = &C[(size_t)grow * N + bn + c4 * 4];
                    atomicAdd(cp + 0, v.x);
                    atomicAdd(cp + 1, v.y);
                    atomicAdd(cp + 2, v.z);
                    atomicAdd(cp + 3, v.w);
                }
            }
        }
    } else {
        #pragma unroll
        for (int i = 0; i < 16; i++) {
            int row = wid * 16 + i;
            int grow = bm + row;
            if (grow < M) {
                #pragma unroll
                for (int hh = 0; hh < 2; hh++) {
                    int c4 = hh * 32 + lane;
                    int pc4 = c4 ^ (row & 31);
                    uint4 v = *(uint4*)(smem + 1024 + row * 1024 + pc4 * 16);
                    *(uint4*)&C[(size_t)grow * N + bn + c4 * 4] = v;
                }
            }
        }
    }
    __syncthreads();
    if (wid == 0)
        asm volatile("tcgen05.dealloc.cta_group::1.sync.aligned.b32 %0, %1;"
                     :: "r"(tmem), "r"(256u));
#else
    /* ---------- SIMT fallback (generic pass; not selected on GB300) ------ */
    __shared__ float As[8][128];
    __shared__ float Bs[8][128];
    int tid = threadIdx.x;
    int bm = blockIdx.y * 128, bn0 = blockIdx.x * 256;
    int Kc = K / gridDim.z;
    int kbase = blockIdx.z * Kc;
    int arow = tid >> 1, acol = (tid & 1) * 4;
    int brow = tid >> 5, bcol = (tid & 31) * 4;
    int tx = tid & 15, ty = tid >> 4;

    for (int half = 0; half < 2; half++) {
        int bn = bn0 + half * 128;
        float acc[8][8];
        #pragma unroll
        for (int i = 0; i < 8; i++)
            #pragma unroll
            for (int j = 0; j < 8; j++) acc[i][j] = 0.f;

        for (int k0 = kbase; k0 < kbase + Kc; k0 += 8) {
            #pragma unroll
            for (int q = 0; q < 4; q++) {
                float v = 0.f;
                if (bm + arow < M) {
                    size_t o = (size_t)(bm + arow) * K + k0 + acol + q;
                    v = __bfloat162float(Ahi[o]) + __bfloat162float(Alo[o]);
                }
                As[acol + q][arow] = v;
            }
            #pragma unroll
            for (int j = 0; j < 4; j++) {
                size_t o = (size_t)(bn + bcol + j) * K + k0 + brow;
                Bs[brow][bcol + j] = __bfloat162float(BhiT[o]) + __bfloat162float(BloT[o]);
            }
            __syncthreads();
            #pragma unroll
            for (int k = 0; k < 8; k++) {
                float a_frag[8], b_frag[8];
                *(float4*)&a_frag[0] = *(const float4*)&As[k][ty * 8];
                *(float4*)&a_frag[4] = *(const float4*)&As[k][ty * 8 + 4];
                *(float4*)&b_frag[0] = *(const float4*)&Bs[k][tx * 8];
                *(float4*)&b_frag[4] = *(const float4*)&Bs[k][tx * 8 + 4];
                #pragma unroll
                for (int i = 0; i < 8; i++)
                    #pragma unroll
                    for (int j = 0; j < 8; j++)
                        acc[i][j] += a_frag[i] * b_frag[j];
            }
            __syncthreads();
        }
        #pragma unroll
        for (int i = 0; i < 8; i++) {
            int row = bm + ty * 8 + i;
            if (row >= M) continue;
            if (ohi) {
                float ss = 0.f, dd = 0.f;
                #pragma unroll
                for (int j = 0; j < 8; j++) {
                    int c = bn + tx * 8 + j;
                    float v = fmaxf(acc[i][j] + bias[c], 0.f);
                    ss += v * ws[c];
                    dd += v * wd[c];
                    __nv_bfloat16 hb, lb;
                    split1(v, &hb, &lb);
                    ohi[(size_t)row * N + c] = hb;
                    olo[(size_t)row * N + c] = lb;
                }
                atomicAdd(&gs[row], ss);
                atomicAdd(&gd[row], dd);
            } else if (gridDim.z > 1) {
                #pragma unroll
                for (int j = 0; j < 8; j++)
                    atomicAdd(&C[(size_t)row * N + bn + tx * 8 + j], acc[i][j]);
            } else {
                #pragma unroll
                for (int j = 0; j < 8; j += 4) {
                    float4 v = make_float4(acc[i][j], acc[i][j+1], acc[i][j+2], acc[i][j+3]);
                    *(float4*)&C[(size_t)row * N + bn + tx * 8 + j] = v;
                }
            }
        }
        __syncthreads();
    }
#endif
}

/* ---------------- small utility kernels ---------------------------------- */
__global__ void k_zero2_i(int* a, int* b, int n) {
    int i = blockIdx.x * blockDim.x + threadIdx.x;
    if (i < n) { a[i] = 0; b[i] = 0; }
}
__global__ void k_zero2_f(float* a, float* b, int n) {
    int i = blockIdx.x * blockDim.x + threadIdx.x;
    if (i < n) { a[i] = 0.f; b[i] = 0.f; }
}
__global__ void k_zerof(float* a, size_t n) {
    size_t i = (size_t)blockIdx.x * blockDim.x + threadIdx.x;
    size_t i4 = i * 4;
    if (i4 + 3 < n) *(float4*)&a[i4] = make_float4(0.f, 0.f, 0.f, 0.f);
}

/* ---------------- CSR build (by dst) -------------------------------------- */
__global__ void k_hist(const int* __restrict__ ei) {
    int e = blockIdx.x * blockDim.x + threadIdx.x;
    if (e >= MT) return;
    int dst = (e < NE) ? ei[NE + e] : (e - NE);
    atomicAdd(&g_deg[dst], 1);
}

__global__ void k_scan() {
    __shared__ int sh[1024];
    __shared__ int carry;
    int t = threadIdx.x;
    if (t == 0) { carry = 0; g_rowptr[0] = 0; }
    __syncthreads();
    for (int base = 0; base < NN; base += 1024) {
        int i = base + t;
        int v = (i < NN) ? g_deg[i] : 0;
        sh[t] = v;
        __syncthreads();
        #pragma unroll
        for (int off = 1; off < 1024; off <<= 1) {
            int add = (t >= off) ? sh[t - off] : 0;
            __syncthreads();
            sh[t] += add;
            __syncthreads();
        }
        int c = carry;
        if (i < NN) g_rowptr[i + 1] = sh[t] + c;
        __syncthreads();
        if (t == 0) carry = c + sh[1023];
        __syncthreads();
    }
}

__global__ void k_scatter(const int* __restrict__ ei) {
    int e = blockIdx.x * blockDim.x + threadIdx.x;
    if (e >= MT) return;
    int src, dst;
    if (e < NE) { src = ei[e]; dst = ei[NE + e]; }
    else        { src = e - NE; dst = e - NE; }
    int pos = g_rowptr[dst] + atomicAdd(&g_cursor[dst], 1);
    g_csrc[pos] = src;
}

/* ---------------- per-node segment softmax (warp per node) ---------------- */
__global__ void edge_softmax() {
    int j = (blockIdx.x * blockDim.x + threadIdx.x) >> 5;
    int lane = threadIdx.x & 31;
    if (j >= NN) return;
    int beg = g_rowptr[j], end = g_rowptr[j + 1];
    float dd = g_d[j];
    float m = -1e30f;
    for (int p = beg + lane; p < end; p += 32) {
        float e = g_s[g_csrc[p]] + dd;
        e = (e > 0.f) ? e : 0.2f * e;
        m = fmaxf(m, e);
    }
    #pragma unroll
    for (int off = 16; off > 0; off >>= 1)
        m = fmaxf(m, __shfl_xor_sync(0xffffffffu, m, off));
    float sum = 0.f;
    for (int p = beg + lane; p < end; p += 32) {
        float e = g_s[g_csrc[p]] + dd;
        e = (e > 0.f) ? e : 0.2f * e;
        sum += expf(e - m);
    }
    #pragma unroll
    for (int off = 16; off > 0; off >>= 1)
        sum += __shfl_xor_sync(0xffffffffu, sum, off);
    float inv = 1.f / sum;
    for (int p = beg + lane; p < end; p += 32) {
        float e = g_s[g_csrc[p]] + dd;
        e = (e > 0.f) ? e : 0.2f * e;
        g_alpha[p] = expf(e - m) * inv;
    }
}

/* ---------------- aggregate x (512-dim), emits bf16 hi/lo ------------------ */
__global__ __launch_bounds__(128)
void aggregate512(const float* __restrict__ x)
{
    __shared__ float sal[128];
    __shared__ int   ssr[128];
    int j = blockIdx.x;
    int t = threadIdx.x;
    int beg = g_rowptr[j], end = g_rowptr[j + 1];
    int deg = end - beg;
    float4 acc = make_float4(0.f, 0.f, 0.f, 0.f);

    for (int base = 0; base < deg; base += 128) {
        int n = deg - base; if (n > 128) n = 128;
        if (t < n) { sal[t] = g_alpha[beg + base + t]; ssr[t] = g_csrc[beg + base + t]; }
        __syncthreads();
        #pragma unroll 4
        for (int p = 0; p < n; p++) {
            float al = sal[p];
            float4 v = *(const float4*)(x + (size_t)ssr[p] * K0 + t * 4);
            acc.x += al * v.x; acc.y += al * v.y;
            acc.z += al * v.z; acc.w += al * v.w;
        }
        __syncthreads();
    }
    __nv_bfloat16 hb[4], lb[4];
    split1(acc.x, &hb[0], &lb[0]); split1(acc.y, &hb[1], &lb[1]);
    split1(acc.z, &hb[2], &lb[2]); split1(acc.w, &hb[3], &lb[3]);
    *(uint2*)&g_xahi[(size_t)j * K0 + t * 4] = *(uint2*)hb;
    *(uint2*)&g_xalo[(size_t)j * K0 + t * 4] = *(uint2*)lb;
}

/* ---------------- aggregate, F=1024, emits fp32 --------------------------- */
__global__ __launch_bounds__(256)
void aggregate1024(const float* __restrict__ h, const float* __restrict__ bias,
                   float* __restrict__ out)
{
    __shared__ float sal[128];
    __shared__ int   ssr[128];
    int j = blockIdx.x;
    int t = threadIdx.x;
    int beg = g_rowptr[j], end = g_rowptr[j + 1];
    int deg = end - beg;
    float4 acc = make_float4(0.f, 0.f, 0.f, 0.f);

    for (int base = 0; base < deg; base += 128) {
        int n = deg - base; if (n > 128) n = 128;
        if (t < 128 && t < n) { sal[t] = g_alpha[beg + base + t]; ssr[t] = g_csrc[beg + base + t]; }
        __syncthreads();
        #pragma unroll 4
        for (int p = 0; p < n; p++) {
            float al = sal[p];
            float4 v = *(const float4*)(h + (size_t)ssr[p] * F2 + t * 4);
            acc.x += al * v.x; acc.y += al * v.y;
            acc.z += al * v.z; acc.w += al * v.w;
        }
        __syncthreads();
    }
    int c = t * 4;
    float4 bb = *(const float4*)&bias[c];
    float4 v;
    v.x = fmaxf(acc.x + bb.x, 0.f);
    v.y = fmaxf(acc.y + bb.y, 0.f);
    v.z = fmaxf(acc.z + bb.z, 0.f);
    v.w = fmaxf(acc.w + bb.w, 0.f);
    *(float4*)&out[(size_t)j * F2 + c] = v;
}

/* ---------------- aggregate F=7 + log_softmax (fused) ---------------------- */
__global__ void aggregate3_ls(const float* __restrict__ h, const float* __restrict__ bias,
                              float* __restrict__ out) {
    int j = blockIdx.x * blockDim.x + threadIdx.x;
    if (j >= NN) return;
    int beg = g_rowptr[j], end = g_rowptr[j + 1];
    float acc[F3];
    #pragma unroll
    for (int c = 0; c < F3; c++) acc[c] = 0.f;
    for (int p = beg; p < end; p++) {
        int src = g_csrc[p];
        float al = g_alpha[p];
        #pragma unroll
        for (int c = 0; c < F3; c++) acc[c] += al * h[src * F3 + c];
    }
    float m = -1e30f;
    #pragma unroll
    for (int c = 0; c < F3; c++) { acc[c] += bias[c]; m = fmaxf(m, acc[c]); }
    float s = 0.f;
    #pragma unroll
    for (int c = 0; c < F3; c++) s += expf(acc[c] - m);
    float l = logf(s) + m;
    #pragma unroll
    for (int c = 0; c < F3; c++) out[j * F3 + c] = acc[c] - l;
}

/* ---------------- layer 3 GEMM (N=7) with fused dots ----------------------- */
__global__ void gemm3(const float* __restrict__ A, const float* __restrict__ W,
                      float* __restrict__ C,
                      const float* __restrict__ asrc, const float* __restrict__ adst)
{
    int w = (blockIdx.x * blockDim.x + threadIdx.x) >> 5;
    int lane = threadIdx.x & 31;
    if (w >= NN) return;
    float acc[F3];
    #pragma unroll
    for (int c = 0; c < F3; c++) acc[c] = 0.f;
    for (int k = lane; k < F2; k += 32) {
        float a = A[(size_t)w * F2 + k];
        #pragma unroll
        for (int c = 0; c < F3; c++) acc[c] += a * W[k * F3 + c];
    }
    #pragma unroll
    for (int c = 0; c < F3; c++) {
        #pragma unroll
        for (int off = 16; off > 0; off >>= 1)
            acc[c] += __shfl_xor_sync(0xffffffffu, acc[c], off);
    }
    if (lane == 0) {
        float ss = 0.f, dd = 0.f;
        #pragma unroll
        for (int c = 0; c < F3; c++) {
            C[w * F3 + c] = acc[c];
            ss += acc[c] * asrc[c];
            dd += acc[c] * adst[c];
        }
        g_s[w] = ss;
        g_d[w] = dd;
    }
}

/* ---------------- launch --------------------------------------------------- */
extern "C" void kernel_launch(void* const* d_in, const int* in_sizes, int n_in,
                              void* d_out, int out_size)
{
    const float* x   = (const float*)d_in[0];
    const int*   ei  = (const int*)d_in[1];
    const float* W1  = (const float*)d_in[2];
    const float* as1 = (const float*)d_in[3];
    const float* ad1 = (const float*)d_in[4];
    const float* b1  = (const float*)d_in[5];
    const float* W2  = (const float*)d_in[6];
    const float* as2 = (const float*)d_in[7];
    const float* ad2 = (const float*)d_in[8];
    const float* b2  = (const float*)d_in[9];
    const float* W3  = (const float*)d_in[10];
    const float* as3 = (const float*)d_in[11];
    const float* ad3 = (const float*)d_in[12];
    const float* b3  = (const float*)d_in[13];
    float* out = (float*)d_out;

    float *h2, *o2, *h3, *gs, *gd, *ws1, *wd1, *ws2, *wd2;
    int *deg, *cur;
    __nv_bfloat16 *w1h, *w1l, *w2h, *w2l, *xah, *xal, *a1h, *a1l;
    cudaGetSymbolAddress((void**)&h2,  g_h2);
    cudaGetSymbolAddress((void**)&o2,  g_o2);
    cudaGetSymbolAddress((void**)&h3,  g_h3);
    cudaGetSymbolAddress((void**)&gs,  g_s);
    cudaGetSymbolAddress((void**)&gd,  g_d);
    cudaGetSymbolAddress((void**)&ws1, g_ws1);
    cudaGetSymbolAddress((void**)&wd1, g_wd1);
    cudaGetSymbolAddress((void**)&ws2, g_ws2);
    cudaGetSymbolAddress((void**)&wd2, g_wd2);
    cudaGetSymbolAddress((void**)&deg, g_deg);
    cudaGetSymbolAddress((void**)&cur, g_cursor);
    cudaGetSymbolAddress((void**)&w1h, g_w1hi);
    cudaGetSymbolAddress((void**)&w1l, g_w1lo);
    cudaGetSymbolAddress((void**)&w2h, g_w2hi);
    cudaGetSymbolAddress((void**)&w2l, g_w2lo);
    cudaGetSymbolAddress((void**)&xah, g_xahi);
    cudaGetSymbolAddress((void**)&xal, g_xalo);
    cudaGetSymbolAddress((void**)&a1h, g_a1hi);
    cudaGetSymbolAddress((void**)&a1l, g_a1lo);

    cudaFuncSetAttribute(gemm_tc, cudaFuncAttributeMaxDynamicSharedMemorySize, GEMM_SMEM);

    const int TB = 256;
    int egrid = (MT + TB - 1) / TB;
    int ngrid = (NN + TB - 1) / TB;
    int wgrid = (NN * 32 + TB - 1) / TB;
    int mblk = (NN + 127) / 128;

    /* ---- prep: weight split, MV dot vectors, CSR build ---- */
    tsplit<<<dim3(F1 / 32, K0 / 32), dim3(32, 32)>>>(W1, w1h, w1l, K0, F1);
    tsplit<<<dim3(F2 / 32, F1 / 32), dim3(32, 32)>>>(W2, w2h, w2l, F1, F2);
    mv_rows<<<(K0 * 32 + TB - 1) / TB, TB>>>(W1, as1, ad1, ws1, wd1, K0, F1);
    mv_rows<<<(F1 * 32 + TB - 1) / TB, TB>>>(W2, as2, ad2, ws2, wd2, F1, F2);
    xdots<<<wgrid, TB>>>(x);
    k_zero2_i<<<ngrid, TB>>>(deg, cur, NN);
    k_hist<<<egrid, TB>>>(ei);
    k_scan<<<1, 1024>>>();
    k_scatter<<<egrid, TB>>>(ei);

    /* ---- layer 1: softmax in x-space, aggregate x, GEMM w/ fused epilogue */
    edge_softmax<<<wgrid, TB>>>();
    aggregate512<<<NN, 128>>>(x);
    k_zero2_f<<<ngrid, TB>>>(gs, gd, NN);
    gemm_tc<<<dim3(F1 / 256, mblk, 1), 256, GEMM_SMEM>>>(
        xah, xal, w1h, w1l, (float*)0, a1h, a1l, b1, ws2, wd2, gs, gd, NN, F1, K0);

    /* ---- layer 2: split-K=2 GEMM (atomicAdd into zeroed h2) ---- */
    edge_softmax<<<wgrid, TB>>>();
    k_zerof<<<((size_t)NN * F2 / 4 + TB - 1) / TB, TB>>>(h2, (size_t)NN * F2);
    gemm_tc<<<dim3(F2 / 256, mblk, 2), 256, GEMM_SMEM>>>(
        a1h, a1l, w2h, w2l, h2, (__nv_bfloat16*)0, (__nv_bfloat16*)0,
        (float*)0, (float*)0, (float*)0, (float*)0, (float*)0, NN, F2, F1);
    aggregate1024<<<NN, 256>>>(h2, b2, o2);

    /* ---- layer 3 ---- */
    gemm3<<<wgrid, TB>>>(o2, W3, h3, as3, ad3);
    edge_softmax<<<wgrid, TB>>>();
    aggregate3_ls<<<ngrid, TB>>>(h3, b3, out);
}